// round 2
// baseline (speedup 1.0000x reference)
#include <cuda_runtime.h>
#include <math.h>
#include <stdint.h>

#define T_TOK 4096
#define DIM   2048
#define FFN   5632
#define NE    8
#define NSLOT (T_TOK*2)

// ---------------- device scratch (static: no allocations allowed) ----------
__device__ int   g_counts[NE];
__device__ int   g_offsets[NE];
__device__ int   g_fill[NE];
__device__ int   g_route_idx[NSLOT];
__device__ float g_route_w[NSLOT];
__device__ int   g_sorted_tok[NSLOT];
__device__ float g_sorted_w[NSLOT];
__device__ float g_h[(size_t)NSLOT * FFN];   // 184 MB intermediate h = silu(g)*u

// ---------------- helpers ---------------------------------------------------
__device__ __forceinline__ float tf32r(float x) {
    asm("cvt.rna.tf32.f32 %0, %1;" : "=f"(x) : "f"(x));
    return x;
}

__device__ __forceinline__ void mma_tf32(float c[4], const uint32_t a[4],
                                         uint32_t b0, uint32_t b1) {
    asm volatile(
        "mma.sync.aligned.m16n8k8.row.col.f32.tf32.tf32.f32 "
        "{%0,%1,%2,%3},{%4,%5,%6,%7},{%8,%9},{%0,%1,%2,%3};\n"
        : "+f"(c[0]), "+f"(c[1]), "+f"(c[2]), "+f"(c[3])
        : "r"(a[0]), "r"(a[1]), "r"(a[2]), "r"(a[3]), "r"(b0), "r"(b1));
}

// ---------------- kernel 0: zero counters -----------------------------------
__global__ void zero_kernel() {
    if (threadIdx.x < NE) g_counts[threadIdx.x] = 0;
}

// ---------------- kernel 1: router (exact fp32; selection must match ref) ----
__global__ void router_kernel(const float* __restrict__ x,
                              const float* __restrict__ gw) {
    int t = blockIdx.x;
    const float* xr = x + (size_t)t * DIM;
    float p[NE];
#pragma unroll
    for (int e = 0; e < NE; e++) p[e] = 0.f;
    for (int d = threadIdx.x; d < DIM; d += 256) {
        float xv = xr[d];
#pragma unroll
        for (int e = 0; e < NE; e++) p[e] += xv * gw[e * DIM + d];
    }
    __shared__ float red[8][NE];
    int warp = threadIdx.x >> 5, lane = threadIdx.x & 31;
#pragma unroll
    for (int e = 0; e < NE; e++) {
        float v = p[e];
#pragma unroll
        for (int o = 16; o > 0; o >>= 1) v += __shfl_xor_sync(0xffffffffu, v, o);
        if (lane == 0) red[warp][e] = v;
    }
    __syncthreads();
    if (threadIdx.x == 0) {
        float logit[NE];
#pragma unroll
        for (int e = 0; e < NE; e++) {
            float s = 0.f;
#pragma unroll
            for (int w = 0; w < 8; w++) s += red[w][e];
            logit[e] = s;
        }
        int i0 = 0; float v0 = logit[0];
        int i1 = -1; float v1 = -INFINITY;
#pragma unroll
        for (int e = 1; e < NE; e++) {
            float v = logit[e];
            if (v > v0)      { v1 = v0; i1 = i0; v0 = v; i0 = e; }
            else if (v > v1) { v1 = v;  i1 = e; }
        }
        float e1 = expf(v1 - v0);
        float s  = 1.f + e1;
        g_route_idx[t * 2 + 0] = i0;  g_route_w[t * 2 + 0] = 1.f / s;
        g_route_idx[t * 2 + 1] = i1;  g_route_w[t * 2 + 1] = e1 / s;
        atomicAdd(&g_counts[i0], 1);
        atomicAdd(&g_counts[i1], 1);
    }
}

// ---------------- kernel 2: scan --------------------------------------------
__global__ void scan_kernel() {
    if (threadIdx.x == 0) {
        int off = 0;
        for (int e = 0; e < NE; e++) {
            g_offsets[e] = off;
            g_fill[e]    = off;
            off += g_counts[e];
        }
    }
}

// ---------------- kernel 3: scatter tokens into per-expert lists -------------
__global__ void scatter_kernel() {
    int t = blockIdx.x * blockDim.x + threadIdx.x;
    if (t >= T_TOK) return;
#pragma unroll
    for (int k = 0; k < 2; k++) {
        int e = g_route_idx[t * 2 + k];
        int p = atomicAdd(&g_fill[e], 1);
        g_sorted_tok[p] = t;
        g_sorted_w[p]   = g_route_w[t * 2 + k];
    }
}

// ---------------- kernel 4: out = bias ---------------------------------------
__global__ void init_out_kernel(float* __restrict__ out,
                                const float* __restrict__ bias) {
    int i = blockIdx.x * blockDim.x + threadIdx.x;
    if (i < T_TOK * DIM) out[i] = bias[i & (DIM - 1)];
}

// ---------------- GEMM tiles -------------------------------------------------
#define MT 128
#define NT 128
#define KC 32
#define SSTR 36     // smem row stride in floats: conflict-free, float4-aligned
#define NTHR 512

// kernel 5: grouped GEMM1: g = X·Wg^T, u = X·Wu^T, h = silu(g)*u  -> g_h
// 512 threads, 16 warps (4x4), warp tile 32x32, register-staged double buffer.
__global__ __launch_bounds__(NTHR, 1) void gemm1_kernel(
    const float* __restrict__ x,
    const float* __restrict__ wgate,
    const float* __restrict__ wup) {
    int e = blockIdx.z;
    int cnt = g_counts[e];
    int mbase = blockIdx.y * MT;
    if (mbase >= cnt) return;
    int off   = g_offsets[e];
    int nbase = blockIdx.x * NT;
    const float* wgE = wgate + (size_t)e * FFN * DIM + (size_t)nbase * DIM;
    const float* wuE = wup   + (size_t)e * FFN * DIM + (size_t)nbase * DIM;

    extern __shared__ char dyn[];
    float (*As)[SSTR] = (float (*)[SSTR])dyn;
    float (*Bg)[SSTR] = (float (*)[SSTR])(dyn + MT * SSTR * 4);
    float (*Bu)[SSTR] = (float (*)[SSTR])(dyn + 2 * MT * SSTR * 4);
    int*   stok       = (int*)(dyn + 3 * MT * SSTR * 4);

    int tid = threadIdx.x;
    if (tid < MT) {
        int m = mbase + tid;
        stok[tid] = (m < cnt) ? g_sorted_tok[off + m] : 0;
    }
    __syncthreads();

    int warp = tid >> 5, lane = tid & 31;
    int wm = warp >> 2, wn = warp & 3;   // 4x4 warps, each 32(M)x32(N)

    // register staging (2 float4 per operand per thread per K-tile)
    float4 aS[2], bgS[2], buS[2];
    int r0 = tid >> 3;               // rows covered: tid>>3 and (tid+512)>>3
    int c4 = (tid & 7) << 2;

#define LD_TILE(k0)                                                         \
    {                                                                       \
        _Pragma("unroll")                                                   \
        for (int i = 0; i < 2; i++) {                                       \
            int row = r0 + i * 64;                                          \
            aS[i]  = *(const float4*)(x + (size_t)stok[row] * DIM + (k0) + c4); \
            bgS[i] = *(const float4*)(wgE + (size_t)row * DIM + (k0) + c4); \
            buS[i] = *(const float4*)(wuE + (size_t)row * DIM + (k0) + c4); \
        }                                                                   \
    }

#define ST_TILE()                                                           \
    {                                                                       \
        _Pragma("unroll")                                                   \
        for (int i = 0; i < 2; i++) {                                       \
            int row = r0 + i * 64;                                          \
            float* da = &As[row][c4];                                       \
            da[0] = tf32r(aS[i].x); da[1] = tf32r(aS[i].y);                 \
            da[2] = tf32r(aS[i].z); da[3] = tf32r(aS[i].w);                 \
            float* dg = &Bg[row][c4];                                       \
            dg[0] = tf32r(bgS[i].x); dg[1] = tf32r(bgS[i].y);               \
            dg[2] = tf32r(bgS[i].z); dg[3] = tf32r(bgS[i].w);               \
            float* du = &Bu[row][c4];                                       \
            du[0] = tf32r(buS[i].x); du[1] = tf32r(buS[i].y);               \
            du[2] = tf32r(buS[i].z); du[3] = tf32r(buS[i].w);               \
        }                                                                   \
    }

    float cg[2][4][4], cu[2][4][4];
#pragma unroll
    for (int a = 0; a < 2; a++)
#pragma unroll
        for (int b = 0; b < 4; b++)
#pragma unroll
            for (int r = 0; r < 4; r++) { cg[a][b][r] = 0.f; cu[a][b][r] = 0.f; }

#define COMPUTE()                                                           \
    {                                                                       \
        _Pragma("unroll")                                                   \
        for (int kk = 0; kk < 4; kk++) {                                    \
            int kb = kk * 8;                                                \
            uint32_t a[2][4];                                               \
            _Pragma("unroll")                                               \
            for (int mf = 0; mf < 2; mf++) {                                \
                int r = wm * 32 + mf * 16 + (lane >> 2);                    \
                int c = kb + (lane & 3);                                    \
                a[mf][0] = __float_as_uint(As[r][c]);                       \
                a[mf][1] = __float_as_uint(As[r + 8][c]);                   \
                a[mf][2] = __float_as_uint(As[r][c + 4]);                   \
                a[mf][3] = __float_as_uint(As[r + 8][c + 4]);               \
            }                                                               \
            _Pragma("unroll")                                               \
            for (int nf = 0; nf < 4; nf++) {                                \
                int col = wn * 32 + nf * 8 + (lane >> 2);                   \
                int c   = kb + (lane & 3);                                  \
                uint32_t bg0 = __float_as_uint(Bg[col][c]);                 \
                uint32_t bg1 = __float_as_uint(Bg[col][c + 4]);             \
                uint32_t bu0 = __float_as_uint(Bu[col][c]);                 \
                uint32_t bu1 = __float_as_uint(Bu[col][c + 4]);             \
                _Pragma("unroll")                                           \
                for (int mf = 0; mf < 2; mf++) {                            \
                    mma_tf32(cg[mf][nf], a[mf], bg0, bg1);                  \
                    mma_tf32(cu[mf][nf], a[mf], bu0, bu1);                  \
                }                                                           \
            }                                                               \
        }                                                                   \
    }

    LD_TILE(0);
    ST_TILE();
    __syncthreads();
    for (int k0 = KC; k0 < DIM; k0 += KC) {
        LD_TILE(k0);       // prefetch next K-slice into registers
        COMPUTE();         // consume current smem tile
        __syncthreads();   // everyone done reading smem
        ST_TILE();         // publish next tile
        __syncthreads();
    }
    COMPUTE();

    // epilogue: h = silu(g) * u
#pragma unroll
    for (int mf = 0; mf < 2; mf++) {
#pragma unroll
        for (int nf = 0; nf < 4; nf++) {
#pragma unroll
            for (int r = 0; r < 4; r++) {
                int mrow = wm * 32 + mf * 16 + (lane >> 2) + ((r >= 2) ? 8 : 0);
                int ncol = wn * 32 + nf * 8 + ((lane & 3) * 2) + (r & 1);
                int m = mbase + mrow;
                if (m < cnt) {
                    float g = cg[mf][nf][r], u = cu[mf][nf][r];
                    float s = g / (1.f + expf(-g));
                    g_h[(size_t)(off + m) * FFN + nbase + ncol] = s * u;
                }
            }
        }
    }
#undef LD_TILE
#undef ST_TILE
#undef COMPUTE
}

// kernel 6: grouped GEMM2: y = h · Wo^T, out += route_w * y (atomic)
__global__ __launch_bounds__(NTHR, 1) void gemm2_kernel(
    const float* __restrict__ wout,
    float* __restrict__ out) {
    int e = blockIdx.z;
    int cnt = g_counts[e];
    int mbase = blockIdx.y * MT;
    if (mbase >= cnt) return;
    int off   = g_offsets[e];
    int nbase = blockIdx.x * NT;
    const float* woE = wout + (size_t)e * DIM * FFN + (size_t)nbase * FFN;

    extern __shared__ char dyn[];
    float (*As)[SSTR] = (float (*)[SSTR])dyn;
    float (*Bs)[SSTR] = (float (*)[SSTR])(dyn + MT * SSTR * 4);
    int*   stok       = (int*)(dyn + 2 * MT * SSTR * 4);
    float* swt        = (float*)(dyn + 2 * MT * SSTR * 4 + MT * 4);

    int tid = threadIdx.x;
    if (tid < MT) {
        int m = mbase + tid;
        stok[tid] = (m < cnt) ? g_sorted_tok[off + m] : 0;
        swt[tid]  = (m < cnt) ? g_sorted_w[off + m] : 0.f;
    }
    __syncthreads();

    int warp = tid >> 5, lane = tid & 31;
    int wm = warp >> 2, wn = warp & 3;

    float4 aS[2], bS[2];
    int r0 = tid >> 3;
    int c4 = (tid & 7) << 2;
    int cmax = cnt - 1;

#define LD_TILE2(k0)                                                        \
    {                                                                       \
        _Pragma("unroll")                                                   \
        for (int i = 0; i < 2; i++) {                                       \
            int row = r0 + i * 64;                                          \
            int mm = mbase + row; if (mm > cmax) mm = cmax;                 \
            aS[i] = *(const float4*)(g_h + (size_t)(off + mm) * FFN + (k0) + c4); \
            bS[i] = *(const float4*)(woE + (size_t)row * FFN + (k0) + c4);  \
        }                                                                   \
    }

#define ST_TILE2()                                                          \
    {                                                                       \
        _Pragma("unroll")                                                   \
        for (int i = 0; i < 2; i++) {                                       \
            int row = r0 + i * 64;                                          \
            float* da = &As[row][c4];                                       \
            da[0] = tf32r(aS[i].x); da[1] = tf32r(aS[i].y);                 \
            da[2] = tf32r(aS[i].z); da[3] = tf32r(aS[i].w);                 \
            float* db = &Bs[row][c4];                                       \
            db[0] = tf32r(bS[i].x); db[1] = tf32r(bS[i].y);                 \
            db[2] = tf32r(bS[i].z); db[3] = tf32r(bS[i].w);                 \
        }                                                                   \
    }

    float cc[2][4][4];
#pragma unroll
    for (int a = 0; a < 2; a++)
#pragma unroll
        for (int b = 0; b < 4; b++)
#pragma unroll
            for (int r = 0; r < 4; r++) cc[a][b][r] = 0.f;

#define COMPUTE2()                                                          \
    {                                                                       \
        _Pragma("unroll")                                                   \
        for (int kk = 0; kk < 4; kk++) {                                    \
            int kb = kk * 8;                                                \
            uint32_t a[2][4];                                               \
            _Pragma("unroll")                                               \
            for (int mf = 0; mf < 2; mf++) {                                \
                int r = wm * 32 + mf * 16 + (lane >> 2);                    \
                int c = kb + (lane & 3);                                    \
                a[mf][0] = __float_as_uint(As[r][c]);                       \
                a[mf][1] = __float_as_uint(As[r + 8][c]);                   \
                a[mf][2] = __float_as_uint(As[r][c + 4]);                   \
                a[mf][3] = __float_as_uint(As[r + 8][c + 4]);               \
            }                                                               \
            _Pragma("unroll")                                               \
            for (int nf = 0; nf < 4; nf++) {                                \
                int col = wn * 32 + nf * 8 + (lane >> 2);                   \
                int c   = kb + (lane & 3);                                  \
                uint32_t b0 = __float_as_uint(Bs[col][c]);                  \
                uint32_t b1 = __float_as_uint(Bs[col][c + 4]);              \
                _Pragma("unroll")                                           \
                for (int mf = 0; mf < 2; mf++)                              \
                    mma_tf32(cc[mf][nf], a[mf], b0, b1);                    \
            }                                                               \
        }                                                                   \
    }

    LD_TILE2(0);
    ST_TILE2();
    __syncthreads();
    for (int k0 = KC; k0 < FFN; k0 += KC) {
        LD_TILE2(k0);
        COMPUTE2();
        __syncthreads();
        ST_TILE2();
        __syncthreads();
    }
    COMPUTE2();

#pragma unroll
    for (int mf = 0; mf < 2; mf++) {
#pragma unroll
        for (int nf = 0; nf < 4; nf++) {
#pragma unroll
            for (int r = 0; r < 4; r++) {
                int mrow = wm * 32 + mf * 16 + (lane >> 2) + ((r >= 2) ? 8 : 0);
                int ncol = wn * 32 + nf * 8 + ((lane & 3) * 2) + (r & 1);
                int m = mbase + mrow;
                if (m < cnt) {
                    float val = cc[mf][nf][r] * swt[mrow];
                    atomicAdd(&out[(size_t)stok[mrow] * DIM + nbase + ncol], val);
                }
            }
        }
    }
#undef LD_TILE2
#undef ST_TILE2
#undef COMPUTE2
}

// ---------------- launch -----------------------------------------------------
extern "C" void kernel_launch(void* const* d_in, const int* in_sizes, int n_in,
                              void* d_out, int out_size) {
    const float* x    = (const float*)d_in[0];
    const float* gw   = (const float*)d_in[1];
    const float* wg   = (const float*)d_in[2];
    const float* wu   = (const float*)d_in[3];
    const float* wo   = (const float*)d_in[4];
    const float* bias = (const float*)d_in[5];
    float* out = (float*)d_out;

    const int smem1 = 3 * MT * SSTR * 4 + MT * 4;          // 55808 B
    const int smem2 = 2 * MT * SSTR * 4 + MT * 8;          // 37888 B
    cudaFuncSetAttribute(gemm1_kernel, cudaFuncAttributeMaxDynamicSharedMemorySize, smem1);
    cudaFuncSetAttribute(gemm2_kernel, cudaFuncAttributeMaxDynamicSharedMemorySize, smem2);

    zero_kernel<<<1, 32>>>();
    router_kernel<<<T_TOK, 256>>>(x, gw);
    scan_kernel<<<1, 32>>>();
    scatter_kernel<<<(T_TOK + 255) / 256, 256>>>();
    init_out_kernel<<<(T_TOK * DIM) / 256, 256>>>(out, bias);
    gemm1_kernel<<<dim3(FFN / NT, T_TOK / MT, NE), NTHR, smem1>>>(x, wg, wu);
    gemm2_kernel<<<dim3(DIM / NT, T_TOK / MT, NE), NTHR, smem2>>>(wo, out);
}

// round 6
// speedup vs baseline: 1.1474x; 1.1474x over previous
#include <cuda_runtime.h>
#include <math.h>
#include <stdint.h>

#define T_TOK 4096
#define DIM   2048
#define FFN   5632
#define NE    8
#define NSLOT (T_TOK*2)

// ---------------- device scratch --------------------------------------------
__device__ int   g_counts[NE];
__device__ int   g_offsets[NE];
__device__ int   g_fill[NE];
__device__ int   g_route_idx[NSLOT];
__device__ float g_route_w[NSLOT];
__device__ int   g_sorted_tok[NSLOT];
__device__ float g_sorted_w[NSLOT];
__device__ float g_h[(size_t)NSLOT * FFN];   // intermediate h = silu(g)*u

// ---------------- helpers ----------------------------------------------------
__device__ __forceinline__ float tf32r(float x) {
    asm("cvt.rna.tf32.f32 %0, %1;" : "=f"(x) : "f"(x));
    return x;
}
__device__ __forceinline__ uint32_t smem_u32(const void* p) {
    uint32_t a;
    asm("{ .reg .u64 t; cvta.to.shared.u64 t, %1; cvt.u32.u64 %0, t; }"
        : "=r"(a) : "l"(p));
    return a;
}
__device__ __forceinline__ void cp16(uint32_t saddr, const void* g) {
    asm volatile("cp.async.cg.shared.global [%0], [%1], 16;"
                 :: "r"(saddr), "l"(g) : "memory");
}
__device__ __forceinline__ void cp_commit() {
    asm volatile("cp.async.commit_group;" ::: "memory");
}
__device__ __forceinline__ void cp_wait1() {
    asm volatile("cp.async.wait_group 1;" ::: "memory");
}
__device__ __forceinline__ void mma_tf32(float c[4], const uint32_t a[4],
                                         uint32_t b0, uint32_t b1) {
    asm volatile(
        "mma.sync.aligned.m16n8k8.row.col.f32.tf32.tf32.f32 "
        "{%0,%1,%2,%3},{%4,%5,%6,%7},{%8,%9},{%0,%1,%2,%3};\n"
        : "+f"(c[0]), "+f"(c[1]), "+f"(c[2]), "+f"(c[3])
        : "r"(a[0]), "r"(a[1]), "r"(a[2]), "r"(a[3]), "r"(b0), "r"(b1));
}

// ---------------- small kernels (routing) ------------------------------------
__global__ void zero_kernel() {
    if (threadIdx.x < NE) g_counts[threadIdx.x] = 0;
}

__global__ void router_kernel(const float* __restrict__ x,
                              const float* __restrict__ gw) {
    int t = blockIdx.x;
    const float* xr = x + (size_t)t * DIM;
    float p[NE];
#pragma unroll
    for (int e = 0; e < NE; e++) p[e] = 0.f;
    for (int d = threadIdx.x; d < DIM; d += 256) {
        float xv = xr[d];
#pragma unroll
        for (int e = 0; e < NE; e++) p[e] += xv * gw[e * DIM + d];
    }
    __shared__ float red[8][NE];
    int warp = threadIdx.x >> 5, lane = threadIdx.x & 31;
#pragma unroll
    for (int e = 0; e < NE; e++) {
        float v = p[e];
#pragma unroll
        for (int o = 16; o > 0; o >>= 1) v += __shfl_xor_sync(0xffffffffu, v, o);
        if (lane == 0) red[warp][e] = v;
    }
    __syncthreads();
    if (threadIdx.x == 0) {
        float logit[NE];
#pragma unroll
        for (int e = 0; e < NE; e++) {
            float s = 0.f;
#pragma unroll
            for (int w = 0; w < 8; w++) s += red[w][e];
            logit[e] = s;
        }
        int i0 = 0; float v0 = logit[0];
        int i1 = -1; float v1 = -INFINITY;
#pragma unroll
        for (int e = 1; e < NE; e++) {
            float v = logit[e];
            if (v > v0)      { v1 = v0; i1 = i0; v0 = v; i0 = e; }
            else if (v > v1) { v1 = v;  i1 = e; }
        }
        float e1 = expf(v1 - v0);
        float s  = 1.f + e1;
        g_route_idx[t * 2 + 0] = i0;  g_route_w[t * 2 + 0] = 1.f / s;
        g_route_idx[t * 2 + 1] = i1;  g_route_w[t * 2 + 1] = e1 / s;
        atomicAdd(&g_counts[i0], 1);
        atomicAdd(&g_counts[i1], 1);
    }
}

__global__ void scan_kernel() {
    if (threadIdx.x == 0) {
        int off = 0;
        for (int e = 0; e < NE; e++) {
            g_offsets[e] = off;
            g_fill[e]    = off;
            off += g_counts[e];
        }
    }
}

__global__ void scatter_kernel() {
    int t = blockIdx.x * blockDim.x + threadIdx.x;
    if (t >= T_TOK) return;
#pragma unroll
    for (int k = 0; k < 2; k++) {
        int e = g_route_idx[t * 2 + k];
        int p = atomicAdd(&g_fill[e], 1);
        g_sorted_tok[p] = t;
        g_sorted_w[p]   = g_route_w[t * 2 + k];
    }
}

__global__ void init_out_kernel(float* __restrict__ out,
                                const float* __restrict__ bias) {
    int i = blockIdx.x * blockDim.x + threadIdx.x;
    if (i < T_TOK * DIM) out[i] = bias[i & (DIM - 1)];
}

// ---------------- GEMM config ------------------------------------------------
// CTA tile 128(M) x 128(N), KC=32, 256 threads, 8 warps (2M x 4N), warp 64x32.
// 3-stage cp.async pipeline. SSTR=36 floats (144 B) conflict-free.
#define KC   32
#define SSTR 36
#define ROWB (SSTR*4)           // 144 bytes per smem row
#define TILEB (128*ROWB)        // 18432 bytes per 128-row tile
#define ST1B (3*TILEB)          // gemm1 stage: A + Bg + Bu = 55296
#define ST2B (2*TILEB)          // gemm2 stage: A + B       = 36864
#define SMEM1 (3*ST1B + 512)
#define SMEM2 (3*ST2B + 1024)

// ---------------- gemm1: h = silu(X Wg^T) * (X Wu^T) -------------------------
__global__ __launch_bounds__(256, 1) void gemm1_kernel(
    const float* __restrict__ x,
    const float* __restrict__ wgate,
    const float* __restrict__ wup) {
    int e = blockIdx.z;
    int cnt = g_counts[e];
    int mbase = blockIdx.y * 128;
    if (mbase >= cnt) return;
    int off = g_offsets[e];
    int nbase = blockIdx.x * 128;

    extern __shared__ char sm[];
    uint32_t sb = smem_u32(sm);
    int* stok = (int*)(sm + 3 * ST1B);
    int tid = threadIdx.x;

    if (tid < 128) {
        int m = mbase + tid;
        stok[tid] = g_sorted_tok[off + (m < cnt ? m : cnt - 1)];
    }
    __syncthreads();

    const float* wgE = wgate + (size_t)e * FFN * DIM + (size_t)nbase * DIM;
    const float* wuE = wup   + (size_t)e * FFN * DIM + (size_t)nbase * DIM;

    // cp.async mapping: thread covers rows r_j = (tid>>3)+32j, 16B col (tid&7)
    int rbase = tid >> 3;
    int cseg  = (tid & 7);
    const float *pa[4], *pg[4], *pu[4];
    uint32_t so[4];
#pragma unroll
    for (int j = 0; j < 4; j++) {
        int r = rbase + j * 32;
        pa[j] = x   + (size_t)stok[r] * DIM + cseg * 4;
        pg[j] = wgE + (size_t)r * DIM + cseg * 4;
        pu[j] = wuE + (size_t)r * DIM + cseg * 4;
        so[j] = (uint32_t)(r * ROWB + cseg * 16);
    }

#define ISSUE1(k0, s)                                                       \
    do {                                                                    \
        uint32_t base = sb + (s) * ST1B;                                    \
        _Pragma("unroll")                                                   \
        for (int j = 0; j < 4; j++) {                                       \
            cp16(base + so[j],             pa[j] + (k0));                   \
            cp16(base + TILEB + so[j],     pg[j] + (k0));                   \
            cp16(base + 2*TILEB + so[j],   pu[j] + (k0));                   \
        }                                                                   \
        cp_commit();                                                        \
    } while (0)

    int warp = tid >> 5, lane = tid & 31;
    int wm = warp >> 2, wn = warp & 3;        // 2 x 4
    int lr = lane >> 2, lc = lane & 3;

    float cg[4][4][4], cu[4][4][4];
#pragma unroll
    for (int a = 0; a < 4; a++)
#pragma unroll
        for (int b = 0; b < 4; b++)
#pragma unroll
            for (int r = 0; r < 4; r++) { cg[a][b][r] = 0.f; cu[a][b][r] = 0.f; }

    ISSUE1(0, 0);
    ISSUE1(KC, 1);

    const int NK = DIM / KC;   // 64
#pragma unroll 1
    for (int kt = 0; kt < NK; kt++) {
        cp_wait1();
        __syncthreads();
        if (kt + 2 < NK) {
            ISSUE1((kt + 2) * KC, (kt + 2) % 3);
        } else {
            cp_commit();
        }
        int s = kt % 3;
        const float (*As)[SSTR] = (const float (*)[SSTR])(sm + s * ST1B);
        const float (*Bg)[SSTR] = (const float (*)[SSTR])(sm + s * ST1B + TILEB);
        const float (*Bu)[SSTR] = (const float (*)[SSTR])(sm + s * ST1B + 2 * TILEB);
#pragma unroll
        for (int kk = 0; kk < 4; kk++) {
            int kb = kk * 8;
            int c = kb + lc;
            uint32_t a[4][4];
#pragma unroll
            for (int mf = 0; mf < 4; mf++) {
                int r = wm * 64 + mf * 16 + lr;
                a[mf][0] = __float_as_uint(tf32r(As[r][c]));
                a[mf][1] = __float_as_uint(tf32r(As[r + 8][c]));
                a[mf][2] = __float_as_uint(tf32r(As[r][c + 4]));
                a[mf][3] = __float_as_uint(tf32r(As[r + 8][c + 4]));
            }
#pragma unroll
            for (int nf = 0; nf < 4; nf++) {
                int col = wn * 32 + nf * 8 + lr;
                uint32_t bg0 = __float_as_uint(tf32r(Bg[col][c]));
                uint32_t bg1 = __float_as_uint(tf32r(Bg[col][c + 4]));
                uint32_t bu0 = __float_as_uint(tf32r(Bu[col][c]));
                uint32_t bu1 = __float_as_uint(tf32r(Bu[col][c + 4]));
#pragma unroll
                for (int mf = 0; mf < 4; mf++) {
                    mma_tf32(cg[mf][nf], a[mf], bg0, bg1);
                    mma_tf32(cu[mf][nf], a[mf], bu0, bu1);
                }
            }
        }
    }

    // epilogue: h = silu(g) * u
#pragma unroll
    for (int mf = 0; mf < 4; mf++) {
#pragma unroll
        for (int half = 0; half < 2; half++) {
            int mrow = wm * 64 + mf * 16 + lr + half * 8;
            int m = mbase + mrow;
            if (m < cnt) {
                float* hp = g_h + (size_t)(off + m) * FFN + nbase + wn * 32;
#pragma unroll
                for (int nf = 0; nf < 4; nf++) {
                    float g0 = cg[mf][nf][half * 2 + 0];
                    float g1 = cg[mf][nf][half * 2 + 1];
                    float u0 = cu[mf][nf][half * 2 + 0];
                    float u1 = cu[mf][nf][half * 2 + 1];
                    float2 hv;
                    hv.x = u0 * g0 / (1.f + __expf(-g0));
                    hv.y = u1 * g1 / (1.f + __expf(-g1));
                    *(float2*)(hp + nf * 8 + lc * 2) = hv;
                }
            }
        }
    }
#undef ISSUE1
}

// ---------------- gemm2: out += w * (h Wo^T) ---------------------------------
__global__ __launch_bounds__(256, 1) void gemm2_kernel(
    const float* __restrict__ wout,
    float* __restrict__ out) {
    int e = blockIdx.z;
    int cnt = g_counts[e];
    int mbase = blockIdx.y * 128;
    if (mbase >= cnt) return;
    int off = g_offsets[e];
    int nbase = blockIdx.x * 128;

    extern __shared__ char sm[];
    uint32_t sb = smem_u32(sm);
    int*   stok = (int*)(sm + 3 * ST2B);
    float* swt  = (float*)(sm + 3 * ST2B + 512);
    int tid = threadIdx.x;

    if (tid < 128) {
        int m = mbase + tid;
        int mc = m < cnt ? m : cnt - 1;
        stok[tid] = g_sorted_tok[off + mc];
        swt[tid]  = (m < cnt) ? g_sorted_w[off + m] : 0.f;
    }
    __syncthreads();

    const float* woE = wout + (size_t)e * DIM * FFN + (size_t)nbase * FFN;

    int rbase = tid >> 3;
    int cseg  = (tid & 7);
    const float *pa[4], *pb[4];
    uint32_t so[4];
#pragma unroll
    for (int j = 0; j < 4; j++) {
        int r = rbase + j * 32;
        int mc = mbase + r; if (mc > cnt - 1) mc = cnt - 1;
        pa[j] = g_h + (size_t)(off + mc) * FFN + cseg * 4;
        pb[j] = woE + (size_t)r * FFN + cseg * 4;
        so[j] = (uint32_t)(r * ROWB + cseg * 16);
    }

#define ISSUE2(k0, s)                                                       \
    do {                                                                    \
        uint32_t base = sb + (s) * ST2B;                                    \
        _Pragma("unroll")                                                   \
        for (int j = 0; j < 4; j++) {                                       \
            cp16(base + so[j],         pa[j] + (k0));                       \
            cp16(base + TILEB + so[j], pb[j] + (k0));                       \
        }                                                                   \
        cp_commit();                                                        \
    } while (0)

    int warp = tid >> 5, lane = tid & 31;
    int wm = warp >> 2, wn = warp & 3;
    int lr = lane >> 2, lc = lane & 3;

    float cc[4][4][4];
#pragma unroll
    for (int a = 0; a < 4; a++)
#pragma unroll
        for (int b = 0; b < 4; b++)
#pragma unroll
            for (int r = 0; r < 4; r++) cc[a][b][r] = 0.f;

    ISSUE2(0, 0);
    ISSUE2(KC, 1);

    const int NK = FFN / KC;   // 176
#pragma unroll 1
    for (int kt = 0; kt < NK; kt++) {
        cp_wait1();
        __syncthreads();
        if (kt + 2 < NK) {
            ISSUE2((kt + 2) * KC, (kt + 2) % 3);
        } else {
            cp_commit();
        }
        int s = kt % 3;
        const float (*As)[SSTR] = (const float (*)[SSTR])(sm + s * ST2B);
        const float (*Bs)[SSTR] = (const float (*)[SSTR])(sm + s * ST2B + TILEB);
#pragma unroll
        for (int kk = 0; kk < 4; kk++) {
            int kb = kk * 8;
            int c = kb + lc;
            uint32_t a[4][4];
#pragma unroll
            for (int mf = 0; mf < 4; mf++) {
                int r = wm * 64 + mf * 16 + lr;
                a[mf][0] = __float_as_uint(tf32r(As[r][c]));
                a[mf][1] = __float_as_uint(tf32r(As[r + 8][c]));
                a[mf][2] = __float_as_uint(tf32r(As[r][c + 4]));
                a[mf][3] = __float_as_uint(tf32r(As[r + 8][c + 4]));
            }
#pragma unroll
            for (int nf = 0; nf < 4; nf++) {
                int col = wn * 32 + nf * 8 + lr;
                uint32_t b0 = __float_as_uint(tf32r(Bs[col][c]));
                uint32_t b1 = __float_as_uint(tf32r(Bs[col][c + 4]));
#pragma unroll
                for (int mf = 0; mf < 4; mf++)
                    mma_tf32(cc[mf][nf], a[mf], b0, b1);
            }
        }
    }

    // epilogue: out += w * y
#pragma unroll
    for (int mf = 0; mf < 4; mf++) {
#pragma unroll
        for (int half = 0; half < 2; half++) {
            int mrow = wm * 64 + mf * 16 + lr + half * 8;
            int m = mbase + mrow;
            if (m < cnt) {
                float wgt = swt[mrow];
                float* op = out + (size_t)stok[mrow] * DIM + nbase + wn * 32;
#pragma unroll
                for (int nf = 0; nf < 4; nf++) {
                    atomicAdd(op + nf * 8 + lc * 2,     cc[mf][nf][half * 2 + 0] * wgt);
                    atomicAdd(op + nf * 8 + lc * 2 + 1, cc[mf][nf][half * 2 + 1] * wgt);
                }
            }
        }
    }
#undef ISSUE2
}

// ---------------- launch -----------------------------------------------------
extern "C" void kernel_launch(void* const* d_in, const int* in_sizes, int n_in,
                              void* d_out, int out_size) {
    const float* x    = (const float*)d_in[0];
    const float* gw   = (const float*)d_in[1];
    const float* wg   = (const float*)d_in[2];
    const float* wu   = (const float*)d_in[3];
    const float* wo   = (const float*)d_in[4];
    const float* bias = (const float*)d_in[5];
    float* out = (float*)d_out;

    cudaFuncSetAttribute(gemm1_kernel, cudaFuncAttributeMaxDynamicSharedMemorySize, SMEM1);
    cudaFuncSetAttribute(gemm2_kernel, cudaFuncAttributeMaxDynamicSharedMemorySize, SMEM2);

    zero_kernel<<<1, 32>>>();
    router_kernel<<<T_TOK, 256>>>(x, gw);
    scan_kernel<<<1, 32>>>();
    scatter_kernel<<<(T_TOK + 255) / 256, 256>>>();
    init_out_kernel<<<(T_TOK * DIM) / 256, 256>>>(out, bias);
    gemm1_kernel<<<dim3(FFN / 128, T_TOK / 128, NE), 256, SMEM1>>>(x, wg, wu);
    gemm2_kernel<<<dim3(DIM / 128, T_TOK / 128, NE), 256, SMEM2>>>(wo, out);
}

// round 8
// speedup vs baseline: 1.7166x; 1.4961x over previous
#include <cuda_runtime.h>
#include <cuda_fp16.h>
#include <math.h>
#include <stdint.h>

#define T_TOK 4096
#define DIM   2048
#define FFN   5632
#define NE    8
#define NSLOT (T_TOK*2)

// ---------------- device scratch --------------------------------------------
__device__ int    g_counts[NE];
__device__ int    g_offsets[NE];
__device__ int    g_fill[NE];
__device__ int    g_route_idx[NSLOT];
__device__ float  g_route_w[NSLOT];
__device__ int    g_sorted_tok[NSLOT];
__device__ float  g_sorted_w[NSLOT];
__device__ __half g_xh[(size_t)T_TOK * DIM];     // 16.8 MB
__device__ __half g_wgh[(size_t)NE * FFN * DIM]; // 184 MB
__device__ __half g_wuh[(size_t)NE * FFN * DIM]; // 184 MB
__device__ __half g_woh[(size_t)NE * DIM * FFN]; // 184 MB
__device__ __half g_hh[(size_t)NSLOT * FFN];     // 92 MB

// ---------------- helpers ----------------------------------------------------
__device__ __forceinline__ uint32_t smem_u32(const void* p) {
    uint32_t a;
    asm("{ .reg .u64 t; cvta.to.shared.u64 t, %1; cvt.u32.u64 %0, t; }"
        : "=r"(a) : "l"(p));
    return a;
}
__device__ __forceinline__ void cp8(uint32_t saddr, const void* g) {
    asm volatile("cp.async.ca.shared.global [%0], [%1], 8;"
                 :: "r"(saddr), "l"(g) : "memory");
}
__device__ __forceinline__ void cp_commit() {
    asm volatile("cp.async.commit_group;" ::: "memory");
}
__device__ __forceinline__ void cp_wait1() {
    asm volatile("cp.async.wait_group 1;" ::: "memory");
}
__device__ __forceinline__ void mma_f16(float c[4], uint32_t a0, uint32_t a1,
                                        uint32_t a2, uint32_t a3,
                                        uint32_t b0, uint32_t b1) {
    asm volatile(
        "mma.sync.aligned.m16n8k16.row.col.f32.f16.f16.f32 "
        "{%0,%1,%2,%3},{%4,%5,%6,%7},{%8,%9},{%0,%1,%2,%3};\n"
        : "+f"(c[0]), "+f"(c[1]), "+f"(c[2]), "+f"(c[3])
        : "r"(a0), "r"(a1), "r"(a2), "r"(a3), "r"(b0), "r"(b1));
}

// ---------------- conversion: fp32 -> fp16 ------------------------------------
__global__ void cvt_kernel(const float* __restrict__ src,
                           __half* __restrict__ dst, int n4) {
    int i = blockIdx.x * blockDim.x + threadIdx.x;
    if (i < n4) {
        float4 v = ((const float4*)src)[i];
        __half2 h0 = __floats2half2_rn(v.x, v.y);
        __half2 h1 = __floats2half2_rn(v.z, v.w);
        uint2 o;
        o.x = *(uint32_t*)&h0;
        o.y = *(uint32_t*)&h1;
        ((uint2*)dst)[i] = o;
    }
}

// ---------------- small kernels (routing) ------------------------------------
__global__ void zero_kernel() {
    if (threadIdx.x < NE) g_counts[threadIdx.x] = 0;
}

__global__ void router_kernel(const float* __restrict__ x,
                              const float* __restrict__ gw) {
    int t = blockIdx.x;
    const float* xr = x + (size_t)t * DIM;
    float p[NE];
#pragma unroll
    for (int e = 0; e < NE; e++) p[e] = 0.f;
    for (int d = threadIdx.x; d < DIM; d += 256) {
        float xv = xr[d];
#pragma unroll
        for (int e = 0; e < NE; e++) p[e] += xv * gw[e * DIM + d];
    }
    __shared__ float red[8][NE];
    int warp = threadIdx.x >> 5, lane = threadIdx.x & 31;
#pragma unroll
    for (int e = 0; e < NE; e++) {
        float v = p[e];
#pragma unroll
        for (int o = 16; o > 0; o >>= 1) v += __shfl_xor_sync(0xffffffffu, v, o);
        if (lane == 0) red[warp][e] = v;
    }
    __syncthreads();
    if (threadIdx.x == 0) {
        float logit[NE];
#pragma unroll
        for (int e = 0; e < NE; e++) {
            float s = 0.f;
#pragma unroll
            for (int w = 0; w < 8; w++) s += red[w][e];
            logit[e] = s;
        }
        int i0 = 0; float v0 = logit[0];
        int i1 = -1; float v1 = -INFINITY;
#pragma unroll
        for (int e = 1; e < NE; e++) {
            float v = logit[e];
            if (v > v0)      { v1 = v0; i1 = i0; v0 = v; i0 = e; }
            else if (v > v1) { v1 = v;  i1 = e; }
        }
        float e1 = expf(v1 - v0);
        float s  = 1.f + e1;
        g_route_idx[t * 2 + 0] = i0;  g_route_w[t * 2 + 0] = 1.f / s;
        g_route_idx[t * 2 + 1] = i1;  g_route_w[t * 2 + 1] = e1 / s;
        atomicAdd(&g_counts[i0], 1);
        atomicAdd(&g_counts[i1], 1);
    }
}

__global__ void scan_kernel() {
    if (threadIdx.x == 0) {
        int off = 0;
        for (int e = 0; e < NE; e++) {
            g_offsets[e] = off;
            g_fill[e]    = off;
            off += g_counts[e];
        }
    }
}

__global__ void scatter_kernel() {
    int t = blockIdx.x * blockDim.x + threadIdx.x;
    if (t >= T_TOK) return;
#pragma unroll
    for (int k = 0; k < 2; k++) {
        int e = g_route_idx[t * 2 + k];
        int p = atomicAdd(&g_fill[e], 1);
        g_sorted_tok[p] = t;
        g_sorted_w[p]   = g_route_w[t * 2 + k];
    }
}

__global__ void init_out_kernel(float* __restrict__ out,
                                const float* __restrict__ bias) {
    int i = blockIdx.x * blockDim.x + threadIdx.x;
    if (i < T_TOK * DIM) out[i] = bias[i & (DIM - 1)];
}

// ---------------- GEMM config ------------------------------------------------
// CTA 128(M) x 128(N), KC=32 halfs, 256 thr, 8 warps (2M x 4N), warp 64x32.
// fp16 smem rows: 32 data halfs + 8 pad = pitch 40 halfs (80 B), conflict-free.
#define KC     32
#define HPITCH 40
#define ROWB   (HPITCH*2)        // 80 bytes
#define TILEB  (128*ROWB)        // 10240 bytes per operand tile
#define ST1B   (3*TILEB)         // gemm1 stage (A,Bg,Bu) = 30720
#define ST2B   (2*TILEB)         // gemm2 stage (A,B)     = 20480
#define SMEM1  (3*ST1B + 512)
#define SMEM2  (3*ST2B + 1024)

// ---------------- gemm1: h = silu(X Wg^T) * (X Wu^T) (fp16 in, fp16 out) -----
__global__ __launch_bounds__(256, 1) void gemm1_kernel() {
    int e = blockIdx.z;
    int cnt = g_counts[e];
    int mbase = blockIdx.y * 128;
    if (mbase >= cnt) return;
    int off = g_offsets[e];
    int nbase = blockIdx.x * 128;

    extern __shared__ char sm[];
    uint32_t sb = smem_u32(sm);
    int* stok = (int*)(sm + 3 * ST1B);
    int tid = threadIdx.x;

    if (tid < 128) {
        int m = mbase + tid;
        stok[tid] = g_sorted_tok[off + (m < cnt ? m : cnt - 1)];
    }
    __syncthreads();

    const __half* wgE = g_wgh + (size_t)e * FFN * DIM + (size_t)nbase * DIM;
    const __half* wuE = g_wuh + (size_t)e * FFN * DIM + (size_t)nbase * DIM;

    // cp.async mapping: seg s = tid + j*256 -> row = s>>3, 8B-seg = s&7
    const __half *pa[4], *pg[4], *pu[4];
    uint32_t so[4];
#pragma unroll
    for (int j = 0; j < 4; j++) {
        int s = tid + j * 256;
        int r = s >> 3, sg = s & 7;
        pa[j] = g_xh + (size_t)stok[r] * DIM + sg * 4;
        pg[j] = wgE + (size_t)r * DIM + sg * 4;
        pu[j] = wuE + (size_t)r * DIM + sg * 4;
        so[j] = (uint32_t)(r * ROWB + sg * 8);
    }

#define ISSUE1(k0, s)                                                       \
    do {                                                                    \
        uint32_t base = sb + (s) * ST1B;                                    \
        _Pragma("unroll")                                                   \
        for (int j = 0; j < 4; j++) {                                       \
            cp8(base + so[j],             pa[j] + (k0));                    \
            cp8(base + TILEB + so[j],     pg[j] + (k0));                    \
            cp8(base + 2*TILEB + so[j],   pu[j] + (k0));                    \
        }                                                                   \
        cp_commit();                                                        \
    } while (0)

    int warp = tid >> 5, lane = tid & 31;
    int wm = warp >> 2, wn = warp & 3;        // 2 x 4
    int lr = lane >> 2, lc = lane & 3;

    float cg[4][4][4], cu[4][4][4];
#pragma unroll
    for (int a = 0; a < 4; a++)
#pragma unroll
        for (int b = 0; b < 4; b++)
#pragma unroll
            for (int r = 0; r < 4; r++) { cg[a][b][r] = 0.f; cu[a][b][r] = 0.f; }

    ISSUE1(0, 0);
    ISSUE1(KC, 1);

    const int NK = DIM / KC;   // 64
#pragma unroll 1
    for (int kt = 0; kt < NK; kt++) {
        cp_wait1();
        __syncthreads();
        if (kt + 2 < NK) {
            ISSUE1((kt + 2) * KC, (kt + 2) % 3);
        } else {
            cp_commit();
        }
        int s = kt % 3;
        const __half (*As)[HPITCH] = (const __half (*)[HPITCH])(sm + s * ST1B);
        const __half (*Bg)[HPITCH] = (const __half (*)[HPITCH])(sm + s * ST1B + TILEB);
        const __half (*Bu)[HPITCH] = (const __half (*)[HPITCH])(sm + s * ST1B + 2 * TILEB);
#pragma unroll
        for (int kk = 0; kk < 2; kk++) {
            int kb = kk * 16;
            int c  = kb + 2 * lc;
            uint32_t a[4][4];
#pragma unroll
            for (int mf = 0; mf < 4; mf++) {
                int r = wm * 64 + mf * 16 + lr;
                a[mf][0] = *(const uint32_t*)&As[r][c];
                a[mf][1] = *(const uint32_t*)&As[r + 8][c];
                a[mf][2] = *(const uint32_t*)&As[r][c + 8];
                a[mf][3] = *(const uint32_t*)&As[r + 8][c + 8];
            }
#pragma unroll
            for (int nf = 0; nf < 4; nf++) {
                int col = wn * 32 + nf * 8 + lr;
                uint32_t bg0 = *(const uint32_t*)&Bg[col][c];
                uint32_t bg1 = *(const uint32_t*)&Bg[col][c + 8];
                uint32_t bu0 = *(const uint32_t*)&Bu[col][c];
                uint32_t bu1 = *(const uint32_t*)&Bu[col][c + 8];
#pragma unroll
                for (int mf = 0; mf < 4; mf++) {
                    mma_f16(cg[mf][nf], a[mf][0], a[mf][1], a[mf][2], a[mf][3], bg0, bg1);
                    mma_f16(cu[mf][nf], a[mf][0], a[mf][1], a[mf][2], a[mf][3], bu0, bu1);
                }
            }
        }
    }

    // epilogue: h = silu(g) * u -> fp16
#pragma unroll
    for (int mf = 0; mf < 4; mf++) {
#pragma unroll
        for (int half = 0; half < 2; half++) {
            int mrow = wm * 64 + mf * 16 + lr + half * 8;
            int m = mbase + mrow;
            if (m < cnt) {
                __half* hp = g_hh + (size_t)(off + m) * FFN + nbase + wn * 32;
#pragma unroll
                for (int nf = 0; nf < 4; nf++) {
                    float g0 = cg[mf][nf][half * 2 + 0];
                    float g1 = cg[mf][nf][half * 2 + 1];
                    float u0 = cu[mf][nf][half * 2 + 0];
                    float u1 = cu[mf][nf][half * 2 + 1];
                    float h0 = u0 * g0 / (1.f + __expf(-g0));
                    float h1 = u1 * g1 / (1.f + __expf(-g1));
                    *(__half2*)(hp + nf * 8 + lc * 2) = __floats2half2_rn(h0, h1);
                }
            }
        }
    }
#undef ISSUE1
}

// ---------------- gemm2: out += w * (h Wo^T), fp16 inputs --------------------
__global__ __launch_bounds__(256, 1) void gemm2_kernel(float* __restrict__ out) {
    int e = blockIdx.z;
    int cnt = g_counts[e];
    int mbase = blockIdx.y * 128;
    if (mbase >= cnt) return;
    int off = g_offsets[e];
    int nbase = blockIdx.x * 128;

    extern __shared__ char sm[];
    uint32_t sb = smem_u32(sm);
    int*   stok = (int*)(sm + 3 * ST2B);
    float* swt  = (float*)(sm + 3 * ST2B + 512);
    int tid = threadIdx.x;

    if (tid < 128) {
        int m = mbase + tid;
        int mc = m < cnt ? m : cnt - 1;
        stok[tid] = g_sorted_tok[off + mc];
        swt[tid]  = (m < cnt) ? g_sorted_w[off + m] : 0.f;
    }
    __syncthreads();

    const __half* woE = g_woh + (size_t)e * DIM * FFN + (size_t)nbase * FFN;

    const __half *pa[4], *pb[4];
    uint32_t so[4];
#pragma unroll
    for (int j = 0; j < 4; j++) {
        int s = tid + j * 256;
        int r = s >> 3, sg = s & 7;
        int mc = mbase + r; if (mc > cnt - 1) mc = cnt - 1;
        pa[j] = g_hh + (size_t)(off + mc) * FFN + sg * 4;
        pb[j] = woE + (size_t)r * FFN + sg * 4;
        so[j] = (uint32_t)(r * ROWB + sg * 8);
    }

#define ISSUE2(k0, s)                                                       \
    do {                                                                    \
        uint32_t base = sb + (s) * ST2B;                                    \
        _Pragma("unroll")                                                   \
        for (int j = 0; j < 4; j++) {                                       \
            cp8(base + so[j],         pa[j] + (k0));                        \
            cp8(base + TILEB + so[j], pb[j] + (k0));                        \
        }                                                                   \
        cp_commit();                                                        \
    } while (0)

    int warp = tid >> 5, lane = tid & 31;
    int wm = warp >> 2, wn = warp & 3;
    int lr = lane >> 2, lc = lane & 3;

    float cc[4][4][4];
#pragma unroll
    for (int a = 0; a < 4; a++)
#pragma unroll
        for (int b = 0; b < 4; b++)
#pragma unroll
            for (int r = 0; r < 4; r++) cc[a][b][r] = 0.f;

    ISSUE2(0, 0);
    ISSUE2(KC, 1);

    const int NK = FFN / KC;   // 176
#pragma unroll 1
    for (int kt = 0; kt < NK; kt++) {
        cp_wait1();
        __syncthreads();
        if (kt + 2 < NK) {
            ISSUE2((kt + 2) * KC, (kt + 2) % 3);
        } else {
            cp_commit();
        }
        int s = kt % 3;
        const __half (*As)[HPITCH] = (const __half (*)[HPITCH])(sm + s * ST2B);
        const __half (*Bs)[HPITCH] = (const __half (*)[HPITCH])(sm + s * ST2B + TILEB);
#pragma unroll
        for (int kk = 0; kk < 2; kk++) {
            int kb = kk * 16;
            int c  = kb + 2 * lc;
            uint32_t a[4][4];
#pragma unroll
            for (int mf = 0; mf < 4; mf++) {
                int r = wm * 64 + mf * 16 + lr;
                a[mf][0] = *(const uint32_t*)&As[r][c];
                a[mf][1] = *(const uint32_t*)&As[r + 8][c];
                a[mf][2] = *(const uint32_t*)&As[r][c + 8];
                a[mf][3] = *(const uint32_t*)&As[r + 8][c + 8];
            }
#pragma unroll
            for (int nf = 0; nf < 4; nf++) {
                int col = wn * 32 + nf * 8 + lr;
                uint32_t b0 = *(const uint32_t*)&Bs[col][c];
                uint32_t b1 = *(const uint32_t*)&Bs[col][c + 8];
#pragma unroll
                for (int mf = 0; mf < 4; mf++)
                    mma_f16(cc[mf][nf], a[mf][0], a[mf][1], a[mf][2], a[mf][3], b0, b1);
            }
        }
    }

    // epilogue: out += w * y
#pragma unroll
    for (int mf = 0; mf < 4; mf++) {
#pragma unroll
        for (int half = 0; half < 2; half++) {
            int mrow = wm * 64 + mf * 16 + lr + half * 8;
            int m = mbase + mrow;
            if (m < cnt) {
                float wgt = swt[mrow];
                float* op = out + (size_t)stok[mrow] * DIM + nbase + wn * 32;
#pragma unroll
                for (int nf = 0; nf < 4; nf++) {
                    atomicAdd(op + nf * 8 + lc * 2,     cc[mf][nf][half * 2 + 0] * wgt);
                    atomicAdd(op + nf * 8 + lc * 2 + 1, cc[mf][nf][half * 2 + 1] * wgt);
                }
            }
        }
    }
#undef ISSUE2
}

// ---------------- launch -----------------------------------------------------
extern "C" void kernel_launch(void* const* d_in, const int* in_sizes, int n_in,
                              void* d_out, int out_size) {
    const float* x    = (const float*)d_in[0];
    const float* gw   = (const float*)d_in[1];
    const float* wg   = (const float*)d_in[2];
    const float* wu   = (const float*)d_in[3];
    const float* wo   = (const float*)d_in[4];
    const float* bias = (const float*)d_in[5];
    float* out = (float*)d_out;

    cudaFuncSetAttribute(gemm1_kernel, cudaFuncAttributeMaxDynamicSharedMemorySize, SMEM1);
    cudaFuncSetAttribute(gemm2_kernel, cudaFuncAttributeMaxDynamicSharedMemorySize, SMEM2);

    __half *xh, *wgh, *wuh, *woh;
    cudaGetSymbolAddress((void**)&xh,  g_xh);
    cudaGetSymbolAddress((void**)&wgh, g_wgh);
    cudaGetSymbolAddress((void**)&wuh, g_wuh);
    cudaGetSymbolAddress((void**)&woh, g_woh);

    const int nW4 = NE * FFN * DIM / 4;   // 23068672
    const int nX4 = T_TOK * DIM / 4;      // 2097152

    zero_kernel<<<1, 32>>>();
    router_kernel<<<T_TOK, 256>>>(x, gw);
    scan_kernel<<<1, 32>>>();
    scatter_kernel<<<(T_TOK + 255) / 256, 256>>>();
    init_out_kernel<<<(T_TOK * DIM) / 256, 256>>>(out, bias);
    cvt_kernel<<<nX4 / 256, 256>>>(x, xh, nX4);
    cvt_kernel<<<nW4 / 256, 256>>>(wg, wgh, nW4);
    cvt_kernel<<<nW4 / 256, 256>>>(wu, wuh, nW4);
    cvt_kernel<<<nW4 / 256, 256>>>(wo, woh, nW4);
    gemm1_kernel<<<dim3(FFN / 128, T_TOK / 128, NE), 256, SMEM1>>>();
    gemm2_kernel<<<dim3(DIM / 128, T_TOK / 128, NE), 256, SMEM2>>>(out);
}